// round 1
// baseline (speedup 1.0000x reference)
#include <cuda_runtime.h>
#include <cuda_bf16.h>
#include <cstdint>

// EnhancedMoEModel: out[b] = sum_e probs[b,e] * sigmoid( relu( relu(x W1e + b1e) W2e + b2e ) W3e + b3e )
// B=524288, D=32, H=64, H2=32, E=8, O=1.
//
// Strategy: warp-tile of 16 rows. Per expert:
//   L1: mma.m16n8k16 bf16, A = x[16,32] (2 k-steps), B = W1 [32,64] (8 n-tiles) -> C f32 [16,64] in regs
//   relu + bf16-pack: C fragments ARE the next A fragments (FA-style chaining)
//   L2: A = h1[16,64] (4 k-steps), B = W2 [64,32] (4 n-tiles) -> C f32 [16,32]
//   L3: per-thread dot with W3 cols + quad shfl reduce -> sigmoid -> prob-weighted accumulate.
// Weights pre-swizzled into bf16 B-fragment layout in shared memory (one-time per CTA).

#define NUM_E 8
#define SMEM_BYTES (4096*8 + 4096*8 + (256+512+256+8)*4)

__device__ __forceinline__ uint32_t packbf(float lo, float hi) {
    __nv_bfloat162 h = __floats2bfloat162_rn(lo, hi);
    return *reinterpret_cast<uint32_t*>(&h);
}

__device__ __forceinline__ void mma16816(float d[4], const uint32_t a[4], uint32_t b0, uint32_t b1) {
    asm volatile(
        "mma.sync.aligned.m16n8k16.row.col.f32.bf16.bf16.f32 "
        "{%0,%1,%2,%3}, {%4,%5,%6,%7}, {%8,%9}, {%0,%1,%2,%3};\n"
        : "+f"(d[0]), "+f"(d[1]), "+f"(d[2]), "+f"(d[3])
        : "r"(a[0]), "r"(a[1]), "r"(a[2]), "r"(a[3]), "r"(b0), "r"(b1));
}

__global__ void __launch_bounds__(256)
moe_kernel(const float* __restrict__ x,
           const float* __restrict__ probs,
           const float* __restrict__ W1, const float* __restrict__ b1,
           const float* __restrict__ W2, const float* __restrict__ b2,
           const float* __restrict__ W3, const float* __restrict__ b3,
           float* __restrict__ out, int NT)
{
    extern __shared__ unsigned char smem_raw[];
    uint2* sW1 = reinterpret_cast<uint2*>(smem_raw);            // 4096 entries (32 KB)
    uint2* sW2 = sW1 + 4096;                                    // 4096 entries (32 KB)
    float* sW3 = reinterpret_cast<float*>(sW2 + 4096);          // 256
    float* sB1 = sW3 + 256;                                     // 512
    float* sB2 = sB1 + 512;                                     // 256
    float* sB3 = sB2 + 256;                                     // 8

    // ---- one-time weight pre-swizzle into mma B-fragment order (bf16x2 pairs) ----
    // B fragment (m16n8k16, col): lane t: b0={B[2c][n],B[2c+1][n]}, b1={B[2c+8][n],B[2c+9][n]},
    // c=t%4, n=t/4.
    for (int idx = threadIdx.x; idx < 4096; idx += blockDim.x) {
        int lanei = idx & 31, j = (idx >> 5) & 7, s = (idx >> 8) & 1, e = idx >> 9;
        int cc = lanei & 3, nn = lanei >> 2;
        int k0 = 16 * s + 2 * cc, col = 8 * j + nn;
        const float* base = W1 + (size_t)e * 32 * 64;
        float v00 = base[(k0    ) * 64 + col];
        float v01 = base[(k0 + 1) * 64 + col];
        float v10 = base[(k0 + 8) * 64 + col];
        float v11 = base[(k0 + 9) * 64 + col];
        sW1[idx] = make_uint2(packbf(v00, v01), packbf(v10, v11));
    }
    for (int idx = threadIdx.x; idx < 4096; idx += blockDim.x) {
        int lanei = idx & 31, j = (idx >> 5) & 3, s = (idx >> 7) & 3, e = idx >> 9;
        int cc = lanei & 3, nn = lanei >> 2;
        int k0 = 16 * s + 2 * cc, col = 8 * j + nn;
        const float* base = W2 + (size_t)e * 64 * 32;
        float v00 = base[(k0    ) * 32 + col];
        float v01 = base[(k0 + 1) * 32 + col];
        float v10 = base[(k0 + 8) * 32 + col];
        float v11 = base[(k0 + 9) * 32 + col];
        sW2[idx] = make_uint2(packbf(v00, v01), packbf(v10, v11));
    }
    for (int idx = threadIdx.x; idx < 256; idx += blockDim.x) sW3[idx] = W3[idx];
    for (int idx = threadIdx.x; idx < 512; idx += blockDim.x) sB1[idx] = b1[idx];
    for (int idx = threadIdx.x; idx < 256; idx += blockDim.x) sB2[idx] = b2[idx];
    if (threadIdx.x < 8) sB3[threadIdx.x] = b3[threadIdx.x];
    __syncthreads();

    const int lane = threadIdx.x & 31;
    const int c = lane & 3;       // quad column index
    const int rq = lane >> 2;     // row within 8-row group
    const int warp_global = blockIdx.x * 8 + (threadIdx.x >> 5);
    const int nwarps = gridDim.x * 8;

    for (int tile = warp_global; tile < NT; tile += nwarps) {
        const int rowbase = tile << 4;

        // ---- load x A-fragments (convert f32 -> bf16x2 on the fly) ----
        // A m16k16 row-major: a0=(r,2c..), a1=(r+8,2c..), a2=(r,2c+8..), a3=(r+8,2c+8..)
        const float* xr0 = x + (size_t)(rowbase + rq) * 32;
        const float* xr1 = xr0 + 8 * 32;
        uint32_t xa[2][4];
        #pragma unroll
        for (int s = 0; s < 2; s++) {
            const int col = 16 * s + 2 * c;
            float2 v00 = *reinterpret_cast<const float2*>(xr0 + col);
            float2 v10 = *reinterpret_cast<const float2*>(xr1 + col);
            float2 v01 = *reinterpret_cast<const float2*>(xr0 + col + 8);
            float2 v11 = *reinterpret_cast<const float2*>(xr1 + col + 8);
            xa[s][0] = packbf(v00.x, v00.y);
            xa[s][1] = packbf(v10.x, v10.y);
            xa[s][2] = packbf(v01.x, v01.y);
            xa[s][3] = packbf(v11.x, v11.y);
        }

        float oa0 = 0.f, oa1 = 0.f;

        #pragma unroll 1
        for (int e = 0; e < NUM_E; e++) {
            // ---- layer 1: [16,32] @ [32,64] ----
            float acc[8][4];
            #pragma unroll
            for (int j = 0; j < 8; j++) { acc[j][0] = acc[j][1] = acc[j][2] = acc[j][3] = 0.f; }
            #pragma unroll
            for (int s = 0; s < 2; s++) {
                #pragma unroll
                for (int j = 0; j < 8; j++) {
                    uint2 b = sW1[(e * 16 + s * 8 + j) * 32 + lane];
                    mma16816(acc[j], xa[s], b.x, b.y);
                }
            }

            // ---- bias + relu + pack: C fragments -> next A fragments ----
            // acc[j] covers h1 cols 8j+2c, 8j+2c+1. k-step s2 of layer2 = n-tiles {2s2, 2s2+1}.
            uint32_t ha[4][4];
            #pragma unroll
            for (int j = 0; j < 8; j++) {
                float bb0 = sB1[e * 64 + 8 * j + 2 * c];
                float bb1 = sB1[e * 64 + 8 * j + 2 * c + 1];
                float c0 = fmaxf(acc[j][0] + bb0, 0.f);
                float c1 = fmaxf(acc[j][1] + bb1, 0.f);
                float c2 = fmaxf(acc[j][2] + bb0, 0.f);
                float c3 = fmaxf(acc[j][3] + bb1, 0.f);
                int s2 = j >> 1, h = j & 1;
                ha[s2][h * 2 + 0] = packbf(c0, c1);
                ha[s2][h * 2 + 1] = packbf(c2, c3);
            }

            // ---- layer 2: [16,64] @ [64,32] ----
            float acc2[4][4];
            #pragma unroll
            for (int j = 0; j < 4; j++) { acc2[j][0] = acc2[j][1] = acc2[j][2] = acc2[j][3] = 0.f; }
            #pragma unroll
            for (int s2 = 0; s2 < 4; s2++) {
                #pragma unroll
                for (int j2 = 0; j2 < 4; j2++) {
                    uint2 b = sW2[(e * 16 + s2 * 4 + j2) * 32 + lane];
                    mma16816(acc2[j2], ha[s2], b.x, b.y);
                }
            }

            // ---- layer 3: bias + relu + dot(W3) + quad reduce ----
            float p0 = 0.f, p1 = 0.f;
            #pragma unroll
            for (int j2 = 0; j2 < 4; j2++) {
                int col = 8 * j2 + 2 * c;
                float w0 = sW3[e * 32 + col], w1 = sW3[e * 32 + col + 1];
                float bb0 = sB2[e * 32 + col], bb1 = sB2[e * 32 + col + 1];
                p0 += fmaxf(acc2[j2][0] + bb0, 0.f) * w0 + fmaxf(acc2[j2][1] + bb1, 0.f) * w1;
                p1 += fmaxf(acc2[j2][2] + bb0, 0.f) * w0 + fmaxf(acc2[j2][3] + bb1, 0.f) * w1;
            }
            p0 += __shfl_xor_sync(0xffffffffu, p0, 1);
            p0 += __shfl_xor_sync(0xffffffffu, p0, 2);
            p1 += __shfl_xor_sync(0xffffffffu, p1, 1);
            p1 += __shfl_xor_sync(0xffffffffu, p1, 2);

            if (c == 0) {
                float z0 = p0 + sB3[e];
                float z1 = p1 + sB3[e];
                float s0 = 1.f / (1.f + __expf(-z0));
                float s1 = 1.f / (1.f + __expf(-z1));
                oa0 += s0 * probs[(size_t)(rowbase + rq) * NUM_E + e];
                oa1 += s1 * probs[(size_t)(rowbase + 8 + rq) * NUM_E + e];
            }
        }

        if (c == 0) {
            out[rowbase + rq] = oa0;
            out[rowbase + 8 + rq] = oa1;
        }
    }
}

extern "C" void kernel_launch(void* const* d_in, const int* in_sizes, int n_in,
                              void* d_out, int out_size) {
    const float* x     = (const float*)d_in[0];
    const float* probs = (const float*)d_in[1];
    const float* W1    = (const float*)d_in[2];
    const float* b1    = (const float*)d_in[3];
    const float* W2    = (const float*)d_in[4];
    const float* b2    = (const float*)d_in[5];
    const float* W3    = (const float*)d_in[6];
    const float* b3    = (const float*)d_in[7];
    float* out = (float*)d_out;

    const int B  = in_sizes[0] / 32;
    const int NT = B / 16;   // B divisible by 16 (524288)

    cudaFuncSetAttribute(moe_kernel, cudaFuncAttributeMaxDynamicSharedMemorySize, SMEM_BYTES);

    const int grid = 304;  // ~2 CTAs per SM, persistent over 32768 tiles
    moe_kernel<<<grid, 256, SMEM_BYTES>>>(x, probs, W1, b1, W2, b2, W3, b3, out, NT);
}